// round 6
// baseline (speedup 1.0000x reference)
#include <cuda_runtime.h>
#include <cuda_bf16.h>
#include <cstdint>

#define MAX_N 50000
#define MAX_E 800000
#define D 128
#define SCAN_B 256
#define MAX_NB ((MAX_N + SCAN_B - 1) / SCAN_B)   // 196

// fused kernel tile config
#define BM 64
#define BN 128
#define BK 16
#define TM 4
#define TN 8
#define SA 65     // sAgg row stride (cols-major, padded)
#define SX 66     // sAs row stride (padded)

// ------------------------- scratch (device globals) -------------------------
__device__ int   g_cnt[MAX_N];                // in-degree
__device__ float g_inv[MAX_N];                // 1/max(deg,1)
__device__ int   g_offs[MAX_N + 1];           // CSR row offsets (by dst)
__device__ int   g_cursor[MAX_N];             // build cursors
__device__ int   g_csr[MAX_E];                // src ids grouped by dst
__device__ float g_zs[(size_t)MAX_N * 4];     // z0,z1 (h@W2l^T), s0,s1 (h@W2r^T+b2)
__device__ int   g_blocksum[MAX_NB];
__device__ int   g_blockbase[MAX_NB];
__device__ int   g_is64;

// ------------------------- helpers ------------------------------------------
__device__ __forceinline__ long long load_idx(const void* ei, long long i) {
    if (g_is64) return ((const long long*)ei)[i];
    return (long long)((const int*)ei)[i];
}

// Zero g_cnt; thread 0 also detects index dtype (int64 => odd 32-bit words all 0).
__global__ void detect_zero_kernel(const void* ei, int n) {
    int i = blockIdx.x * blockDim.x + threadIdx.x;
    if (i < n) g_cnt[i] = 0;
    if (blockIdx.x == 0 && threadIdx.x == 0) {
        const unsigned* u = (const unsigned*)ei;
        int ok = 1;
        for (int k = 0; k < 64; k++)
            if (u[2 * k + 1] != 0u) { ok = 0; break; }
        g_is64 = ok;
    }
}

// ---------------- histogram of dst ------------------------------------------
__global__ void hist_kernel(const void* __restrict__ ei, long long E) {
    long long e = (long long)blockIdx.x * blockDim.x + threadIdx.x;
    if (e >= E) return;
    int d = (int)load_idx(ei, E + e);
    atomicAdd(&g_cnt[d], 1);
}

// ---------------- 3-phase device-wide exclusive scan -------------------------
__global__ __launch_bounds__(SCAN_B)
void scan_p1(int n) {
    __shared__ int wsum[SCAN_B / 32];
    int i = blockIdx.x * SCAN_B + threadIdx.x;
    int lane = threadIdx.x & 31;
    int wid = threadIdx.x >> 5;
    int v = (i < n) ? g_cnt[i] : 0;
    #pragma unroll
    for (int o = 16; o; o >>= 1) v += __shfl_xor_sync(0xffffffffu, v, o);
    if (lane == 0) wsum[wid] = v;
    __syncthreads();
    if (threadIdx.x == 0) {
        int s = 0;
        #pragma unroll
        for (int w = 0; w < SCAN_B / 32; w++) s += wsum[w];
        g_blocksum[blockIdx.x] = s;
    }
}

// All 32 lanes of warp 0 run the 2nd-level scan (full mask; lanes >= 8 carry 0).
__global__ __launch_bounds__(SCAN_B)
void scan_p2(int nb) {
    __shared__ int wsum[SCAN_B / 32];
    int t = threadIdx.x;
    int lane = t & 31;
    int wid = t >> 5;
    int v = (t < nb) ? g_blocksum[t] : 0;
    int inc = v;
    #pragma unroll
    for (int o = 1; o < 32; o <<= 1) {
        int u = __shfl_up_sync(0xffffffffu, inc, o);
        if (lane >= o) inc += u;
    }
    if (lane == 31) wsum[wid] = inc;
    __syncthreads();
    if (wid == 0) {
        int w = (lane < SCAN_B / 32) ? wsum[lane] : 0;
        int winc = w;
        #pragma unroll
        for (int o = 1; o < 32; o <<= 1) {
            int u = __shfl_up_sync(0xffffffffu, winc, o);
            if (lane >= o) winc += u;
        }
        if (lane < SCAN_B / 32) wsum[lane] = winc;
    }
    __syncthreads();
    int base = (wid > 0) ? wsum[wid - 1] : 0;
    if (t < nb) g_blockbase[t] = base + inc - v;
}

__global__ __launch_bounds__(SCAN_B)
void scan_p3(int n) {
    __shared__ int wsum[SCAN_B / 32];
    int i = blockIdx.x * SCAN_B + threadIdx.x;
    int lane = threadIdx.x & 31;
    int wid = threadIdx.x >> 5;
    int c = (i < n) ? g_cnt[i] : 0;
    int inc = c;
    #pragma unroll
    for (int o = 1; o < 32; o <<= 1) {
        int u = __shfl_up_sync(0xffffffffu, inc, o);
        if (lane >= o) inc += u;
    }
    if (lane == 31) wsum[wid] = inc;
    __syncthreads();
    if (wid == 0) {
        int w = (lane < SCAN_B / 32) ? wsum[lane] : 0;
        int winc = w;
        #pragma unroll
        for (int o = 1; o < 32; o <<= 1) {
            int u = __shfl_up_sync(0xffffffffu, winc, o);
            if (lane >= o) winc += u;
        }
        if (lane < SCAN_B / 32) wsum[lane] = winc;
    }
    __syncthreads();
    int wbase = (wid > 0) ? wsum[wid - 1] : 0;
    int off = g_blockbase[blockIdx.x] + wbase + inc - c;
    if (i < n) {
        g_offs[i] = off;
        g_cursor[i] = off;
        g_inv[i] = 1.0f / (float)max(c, 1);
        if (i == n - 1) g_offs[n] = off + c;
    }
}

// ---------------- CSR build --------------------------------------------------
__global__ void build_kernel(const void* __restrict__ ei, long long E) {
    long long e = (long long)blockIdx.x * blockDim.x + threadIdx.x;
    if (e >= E) return;
    int s = (int)load_idx(ei, e);
    int d = (int)load_idx(ei, E + e);
    int p = atomicAdd(&g_cursor[d], 1);
    g_csr[p] = s;
}

// ---------------- fused: gather(64 rows -> smem) + GEMM(K=256) + projection --
// h = relu(agg @ W1l^T + x @ W1r^T + b1); zs = [h@W2l^T, h@W2r^T + b2]
__global__ __launch_bounds__(256, 3)
void fused_kernel(const float* __restrict__ x,
                  const float* __restrict__ W1l, const float* __restrict__ W1r,
                  const float* __restrict__ b1,
                  const float* __restrict__ W2l, const float* __restrict__ W2r,
                  const float* __restrict__ b2, int M) {
    __shared__ float sAgg[D * SA];        // [col][row], stride SA=65  (33.3 KB)
    __shared__ float sAs[BK * SX];        // staged x tile [k][row], stride 66
    __shared__ float sBs[BK * BN];        // staged weight tile [k][col]

    int tid = threadIdx.x;
    int block_row = blockIdx.x * BM;
    int wid = tid >> 5;
    int lane = tid & 31;

    // ---- phase 1: gather neighbor means for rows block_row..block_row+63 ----
    #pragma unroll 1
    for (int rr = 0; rr < 8; rr++) {
        int rl = wid * 8 + rr;            // local row 0..63
        int node = block_row + rl;
        float4 a0 = make_float4(0.f, 0.f, 0.f, 0.f);
        float4 a1 = make_float4(0.f, 0.f, 0.f, 0.f);
        if (node < M) {
            int beg = g_offs[node];
            int end = g_offs[node + 1];
            int k = beg;
            for (; k + 1 < end; k += 2) {
                int s0 = g_csr[k];
                int s1 = g_csr[k + 1];
                float4 v0 = *(const float4*)(x + (size_t)s0 * D + lane * 4);
                float4 v1 = *(const float4*)(x + (size_t)s1 * D + lane * 4);
                a0.x += v0.x; a0.y += v0.y; a0.z += v0.z; a0.w += v0.w;
                a1.x += v1.x; a1.y += v1.y; a1.z += v1.z; a1.w += v1.w;
            }
            if (k < end) {
                int s0 = g_csr[k];
                float4 v0 = *(const float4*)(x + (size_t)s0 * D + lane * 4);
                a0.x += v0.x; a0.y += v0.y; a0.z += v0.z; a0.w += v0.w;
            }
            float inv = g_inv[node];
            a0.x = (a0.x + a1.x) * inv;
            a0.y = (a0.y + a1.y) * inv;
            a0.z = (a0.z + a1.z) * inv;
            a0.w = (a0.w + a1.w) * inv;
        }
        // transposed store: sAgg[col][row]
        sAgg[(lane * 4 + 0) * SA + rl] = a0.x;
        sAgg[(lane * 4 + 1) * SA + rl] = a0.y;
        sAgg[(lane * 4 + 2) * SA + rl] = a0.z;
        sAgg[(lane * 4 + 3) * SA + rl] = a0.w;
    }
    __syncthreads();

    // ---- phase 2: GEMM over K=256 ----
    int tx = tid & 15;                    // col group: cols tx*8..+7
    int ty = tid >> 4;                    // row group: rows ty*4..+3
    float acc[TM][TN];
    #pragma unroll
    for (int i = 0; i < TM; i++)
        #pragma unroll
        for (int j = 0; j < TN; j++) acc[i][j] = 0.f;

    #pragma unroll 1
    for (int kt = 0; kt < 2 * D; kt += BK) {
        bool isAgg = (kt < D);
        int kk0 = isAgg ? kt : kt - D;
        const float* Wptr = isAgg ? W1l : W1r;

        // stage weight tile: sBs[k][j] = W[j][kk0+k]
        #pragma unroll
        for (int p = 0; p < 2; p++) {
            int f = tid + p * 256;
            int j = f >> 2;
            int c4 = (f & 3) * 4;
            float4 v = *(const float4*)(Wptr + (size_t)j * D + kk0 + c4);
            sBs[(c4 + 0) * BN + j] = v.x;
            sBs[(c4 + 1) * BN + j] = v.y;
            sBs[(c4 + 2) * BN + j] = v.z;
            sBs[(c4 + 3) * BN + j] = v.w;
        }
        // stage x tile for self half: sAs[k][r] = x[block_row+r][kk0+k]
        if (!isAgg) {
            int r = tid >> 2;             // 0..63
            int c4 = (tid & 3) * 4;
            int grow = block_row + r;
            float4 v = make_float4(0.f, 0.f, 0.f, 0.f);
            if (grow < M)
                v = *(const float4*)(x + (size_t)grow * D + kk0 + c4);
            sAs[(c4 + 0) * SX + r] = v.x;
            sAs[(c4 + 1) * SX + r] = v.y;
            sAs[(c4 + 2) * SX + r] = v.z;
            sAs[(c4 + 3) * SX + r] = v.w;
        }
        __syncthreads();

        if (isAgg) {
            #pragma unroll
            for (int k = 0; k < BK; k++) {
                float a[TM];
                int abase = (kt + k) * SA + ty * TM;
                #pragma unroll
                for (int i = 0; i < TM; i++) a[i] = sAgg[abase + i];
                float4 b0 = *(const float4*)&sBs[k * BN + tx * TN];
                float4 b1v = *(const float4*)&sBs[k * BN + tx * TN + 4];
                float b[TN] = {b0.x, b0.y, b0.z, b0.w, b1v.x, b1v.y, b1v.z, b1v.w};
                #pragma unroll
                for (int i = 0; i < TM; i++)
                    #pragma unroll
                    for (int j = 0; j < TN; j++)
                        acc[i][j] += a[i] * b[j];
            }
        } else {
            #pragma unroll
            for (int k = 0; k < BK; k++) {
                float a[TM];
                int abase = k * SX + ty * TM;
                #pragma unroll
                for (int i = 0; i < TM; i++) a[i] = sAs[abase + i];
                float4 b0 = *(const float4*)&sBs[k * BN + tx * TN];
                float4 b1v = *(const float4*)&sBs[k * BN + tx * TN + 4];
                float b[TN] = {b0.x, b0.y, b0.z, b0.w, b1v.x, b1v.y, b1v.z, b1v.w};
                #pragma unroll
                for (int i = 0; i < TM; i++)
                    #pragma unroll
                    for (int j = 0; j < TN; j++)
                        acc[i][j] += a[i] * b[j];
            }
        }
        __syncthreads();
    }

    // ---- phase 3: bias + relu + project to z/s ----
    int col0 = tx * TN;
    float wl0[TN], wl1[TN], wr0[TN], wr1[TN], bb1[TN];
    #pragma unroll
    for (int j = 0; j < TN; j += 4) {
        float4 a = *(const float4*)(W2l + col0 + j);
        wl0[j] = a.x; wl0[j+1] = a.y; wl0[j+2] = a.z; wl0[j+3] = a.w;
        float4 b = *(const float4*)(W2l + D + col0 + j);
        wl1[j] = b.x; wl1[j+1] = b.y; wl1[j+2] = b.z; wl1[j+3] = b.w;
        float4 c = *(const float4*)(W2r + col0 + j);
        wr0[j] = c.x; wr0[j+1] = c.y; wr0[j+2] = c.z; wr0[j+3] = c.w;
        float4 d = *(const float4*)(W2r + D + col0 + j);
        wr1[j] = d.x; wr1[j+1] = d.y; wr1[j+2] = d.z; wr1[j+3] = d.w;
        float4 e = *(const float4*)(b1 + col0 + j);
        bb1[j] = e.x; bb1[j+1] = e.y; bb1[j+2] = e.z; bb1[j+3] = e.w;
    }
    float bb2x = b2[0], bb2y = b2[1];

    #pragma unroll
    for (int i = 0; i < TM; i++) {
        int grow = block_row + ty * TM + i;
        float z0 = 0.f, z1 = 0.f, s0 = 0.f, s1 = 0.f;
        #pragma unroll
        for (int j = 0; j < TN; j++) {
            float h = fmaxf(acc[i][j] + bb1[j], 0.f);
            z0 += h * wl0[j];
            z1 += h * wl1[j];
            s0 += h * wr0[j];
            s1 += h * wr1[j];
        }
        #pragma unroll
        for (int o = 8; o; o >>= 1) {
            z0 += __shfl_xor_sync(0xffffffffu, z0, o);
            z1 += __shfl_xor_sync(0xffffffffu, z1, o);
            s0 += __shfl_xor_sync(0xffffffffu, s0, o);
            s1 += __shfl_xor_sync(0xffffffffu, s1, o);
        }
        if (tx == 0 && grow < M) {
            float4 o4;
            o4.x = z0; o4.y = z1;
            o4.z = s0 + bb2x; o4.w = s1 + bb2y;
            *(float4*)(g_zs + (size_t)grow * 4) = o4;
        }
    }
}

// ---------------- layer-2 gather + final output ------------------------------
__global__ __launch_bounds__(256)
void final_kernel(float* __restrict__ out, int M) {
    int node = blockIdx.x * blockDim.x + threadIdx.x;
    if (node >= M) return;
    int beg = g_offs[node];
    int end = g_offs[node + 1];
    float a0 = 0.f, a1 = 0.f;
    #pragma unroll 4
    for (int k = beg; k < end; k++) {
        int s = g_csr[k];
        float2 zv = *(const float2*)(g_zs + (size_t)s * 4);
        a0 += zv.x;
        a1 += zv.y;
    }
    float inv = g_inv[node];
    float2 st = *(const float2*)(g_zs + (size_t)node * 4 + 2);
    float2 o;
    o.x = a0 * inv + st.x;
    o.y = a1 * inv + st.y;
    *(float2*)(out + (size_t)node * 2) = o;
}

// ------------------------- launch -------------------------------------------
extern "C" void kernel_launch(void* const* d_in, const int* in_sizes, int n_in,
                              void* d_out, int out_size) {
    const float* x   = (const float*)d_in[0];
    const void*  ei  = d_in[1];
    const float* W1l = (const float*)d_in[2];
    const float* W1r = (const float*)d_in[3];
    const float* b1  = (const float*)d_in[4];
    const float* W2l = (const float*)d_in[5];
    const float* W2r = (const float*)d_in[6];
    const float* b2  = (const float*)d_in[7];
    float* out = (float*)d_out;

    int M = in_sizes[0] / D;
    long long E = in_sizes[1] / 2;
    int nb = (M + SCAN_B - 1) / SCAN_B;

    detect_zero_kernel<<<(M + 255) / 256, 256>>>(ei, M);          // 0
    hist_kernel<<<(int)((E + 255) / 256), 256>>>(ei, E);          // 1
    scan_p1<<<nb, SCAN_B>>>(M);                                   // 2
    scan_p2<<<1, SCAN_B>>>(nb);                                   // 3
    scan_p3<<<nb, SCAN_B>>>(M);                                   // 4
    build_kernel<<<(int)((E + 255) / 256), 256>>>(ei, E);         // 5
    fused_kernel<<<(M + BM - 1) / BM, 256>>>(x, W1l, W1r, b1,     // 6
                                             W2l, W2r, b2, M);
    final_kernel<<<(M + 255) / 256, 256>>>(out, M);               // 7
}

// round 7
// speedup vs baseline: 1.1593x; 1.1593x over previous
#include <cuda_runtime.h>
#include <cuda_bf16.h>
#include <cstdint>

#define MAX_N 50000
#define MAX_E 800000
#define D 128
#define SCAN_B 256
#define MAX_NB ((MAX_N + SCAN_B - 1) / SCAN_B)   // 196

// ------------------------- scratch (device globals) -------------------------
__device__ float g_agg1[(size_t)MAX_N * D];   // normalized neighbor means
__device__ float g_accs[(size_t)MAX_N * D];   // x @ W1r^T
__device__ int   g_cnt[MAX_N];
__device__ float g_inv[MAX_N];
__device__ int   g_offs[MAX_N + 1];
__device__ int   g_cursor[MAX_N];
__device__ int   g_csr[MAX_E];
__device__ float g_zs[(size_t)MAX_N * 4];     // z0,z1 (h@W2l^T), s0,s1 (h@W2r^T+b2)
__device__ int   g_blocksum[MAX_NB];
__device__ int   g_blockbase[MAX_NB];
__device__ int   g_is64;

// ------------------------- helpers ------------------------------------------
__device__ __forceinline__ long long load_idx(const void* ei, long long i) {
    if (g_is64) return ((const long long*)ei)[i];
    return (long long)((const int*)ei)[i];
}

// Zero g_cnt; thread 0 detects index dtype (int64 => odd 32-bit words all 0).
__global__ void detect_zero_kernel(const void* ei, int n) {
    int i = blockIdx.x * blockDim.x + threadIdx.x;
    if (i < n) g_cnt[i] = 0;
    if (blockIdx.x == 0 && threadIdx.x == 0) {
        const unsigned* u = (const unsigned*)ei;
        int ok = 1;
        for (int k = 0; k < 64; k++)
            if (u[2 * k + 1] != 0u) { ok = 0; break; }
        g_is64 = ok;
    }
}

__global__ void hist_kernel(const void* __restrict__ ei, long long E) {
    long long e = (long long)blockIdx.x * blockDim.x + threadIdx.x;
    if (e >= E) return;
    int d = (int)load_idx(ei, E + e);
    atomicAdd(&g_cnt[d], 1);
}

// ---------------- 3-phase device-wide exclusive scan -------------------------
__global__ __launch_bounds__(SCAN_B)
void scan_p1(int n) {
    __shared__ int wsum[SCAN_B / 32];
    int i = blockIdx.x * SCAN_B + threadIdx.x;
    int lane = threadIdx.x & 31;
    int wid = threadIdx.x >> 5;
    int v = (i < n) ? g_cnt[i] : 0;
    #pragma unroll
    for (int o = 16; o; o >>= 1) v += __shfl_xor_sync(0xffffffffu, v, o);
    if (lane == 0) wsum[wid] = v;
    __syncthreads();
    if (threadIdx.x == 0) {
        int s = 0;
        #pragma unroll
        for (int w = 0; w < SCAN_B / 32; w++) s += wsum[w];
        g_blocksum[blockIdx.x] = s;
    }
}

// All 32 lanes of warp 0 run the 2nd-level scan (full mask; lanes >= 8 carry 0).
__global__ __launch_bounds__(SCAN_B)
void scan_p2(int nb) {
    __shared__ int wsum[SCAN_B / 32];
    int t = threadIdx.x;
    int lane = t & 31;
    int wid = t >> 5;
    int v = (t < nb) ? g_blocksum[t] : 0;
    int inc = v;
    #pragma unroll
    for (int o = 1; o < 32; o <<= 1) {
        int u = __shfl_up_sync(0xffffffffu, inc, o);
        if (lane >= o) inc += u;
    }
    if (lane == 31) wsum[wid] = inc;
    __syncthreads();
    if (wid == 0) {
        int w = (lane < SCAN_B / 32) ? wsum[lane] : 0;
        int winc = w;
        #pragma unroll
        for (int o = 1; o < 32; o <<= 1) {
            int u = __shfl_up_sync(0xffffffffu, winc, o);
            if (lane >= o) winc += u;
        }
        if (lane < SCAN_B / 32) wsum[lane] = winc;
    }
    __syncthreads();
    int base = (wid > 0) ? wsum[wid - 1] : 0;
    if (t < nb) g_blockbase[t] = base + inc - v;
}

__global__ __launch_bounds__(SCAN_B)
void scan_p3(int n) {
    __shared__ int wsum[SCAN_B / 32];
    int i = blockIdx.x * SCAN_B + threadIdx.x;
    int lane = threadIdx.x & 31;
    int wid = threadIdx.x >> 5;
    int c = (i < n) ? g_cnt[i] : 0;
    int inc = c;
    #pragma unroll
    for (int o = 1; o < 32; o <<= 1) {
        int u = __shfl_up_sync(0xffffffffu, inc, o);
        if (lane >= o) inc += u;
    }
    if (lane == 31) wsum[wid] = inc;
    __syncthreads();
    if (wid == 0) {
        int w = (lane < SCAN_B / 32) ? wsum[lane] : 0;
        int winc = w;
        #pragma unroll
        for (int o = 1; o < 32; o <<= 1) {
            int u = __shfl_up_sync(0xffffffffu, winc, o);
            if (lane >= o) winc += u;
        }
        if (lane < SCAN_B / 32) wsum[lane] = winc;
    }
    __syncthreads();
    int wbase = (wid > 0) ? wsum[wid - 1] : 0;
    int off = g_blockbase[blockIdx.x] + wbase + inc - c;
    if (i < n) {
        g_offs[i] = off;
        g_cursor[i] = off;
        g_inv[i] = 1.0f / (float)max(c, 1);
        if (i == n - 1) g_offs[n] = off + c;
    }
}

// ---------------- CSR build --------------------------------------------------
__global__ void build_kernel(const void* __restrict__ ei, long long E) {
    long long e = (long long)blockIdx.x * blockDim.x + threadIdx.x;
    if (e >= E) return;
    int s = (int)load_idx(ei, e);
    int d = (int)load_idx(ei, E + e);
    int p = atomicAdd(&g_cursor[d], 1);
    g_csr[p] = s;
}

// ---------------- layer-1 gather: warp per node ------------------------------
__global__ __launch_bounds__(256)
void agg1_gather(const float* __restrict__ x, int M) {
    int node = (int)(((long long)blockIdx.x * blockDim.x + threadIdx.x) >> 5);
    int lane = threadIdx.x & 31;
    if (node >= M) return;
    int beg = g_offs[node];
    int end = g_offs[node + 1];
    float4 a0 = make_float4(0.f, 0.f, 0.f, 0.f);
    float4 a1 = make_float4(0.f, 0.f, 0.f, 0.f);
    int k = beg;
    for (; k + 1 < end; k += 2) {
        int s0 = g_csr[k];
        int s1 = g_csr[k + 1];
        float4 v0 = *(const float4*)(x + (size_t)s0 * D + lane * 4);
        float4 v1 = *(const float4*)(x + (size_t)s1 * D + lane * 4);
        a0.x += v0.x; a0.y += v0.y; a0.z += v0.z; a0.w += v0.w;
        a1.x += v1.x; a1.y += v1.y; a1.z += v1.z; a1.w += v1.w;
    }
    if (k < end) {
        int s0 = g_csr[k];
        float4 v0 = *(const float4*)(x + (size_t)s0 * D + lane * 4);
        a0.x += v0.x; a0.y += v0.y; a0.z += v0.z; a0.w += v0.w;
    }
    float inv = g_inv[node];
    float4 r;
    r.x = (a0.x + a1.x) * inv;
    r.y = (a0.y + a1.y) * inv;
    r.z = (a0.z + a1.z) * inv;
    r.w = (a0.w + a1.w) * inv;
    *(float4*)(g_agg1 + (size_t)node * D + lane * 4) = r;
}

// ---------------- tiled GEMM pieces ------------------------------------------
#define BM 128
#define BN 128
#define BK 16
#define TM 8
#define TN 8

// gemm_self: g_accs = x @ W1r^T   (K = 128)  — runs on side stream
__global__ __launch_bounds__(256, 2)
void gemm_self_kernel(const float* __restrict__ x, const float* __restrict__ W1r,
                      int M) {
    __shared__ float As[BK][BM];
    __shared__ float Bs[BK][BN];
    int block_row = blockIdx.x * BM;
    int tid = threadIdx.x;
    int tx = tid & 15;
    int ty = tid >> 4;
    float acc[TM][TN];
    #pragma unroll
    for (int i = 0; i < TM; i++)
        #pragma unroll
        for (int j = 0; j < TN; j++) acc[i][j] = 0.f;

    #pragma unroll 1
    for (int kt = 0; kt < D; kt += BK) {
        #pragma unroll
        for (int p = 0; p < 2; p++) {
            int f = tid + p * 256;
            int r = f >> 2;
            int c4 = (f & 3) * 4;
            int grow = block_row + r;
            float4 v = make_float4(0.f, 0.f, 0.f, 0.f);
            if (grow < M)
                v = *(const float4*)(x + (size_t)grow * D + kt + c4);
            As[c4 + 0][r] = v.x; As[c4 + 1][r] = v.y;
            As[c4 + 2][r] = v.z; As[c4 + 3][r] = v.w;
        }
        #pragma unroll
        for (int p = 0; p < 2; p++) {
            int f = tid + p * 256;
            int j = f >> 2;
            int c4 = (f & 3) * 4;
            float4 v = *(const float4*)(W1r + (size_t)j * D + kt + c4);
            Bs[c4 + 0][j] = v.x; Bs[c4 + 1][j] = v.y;
            Bs[c4 + 2][j] = v.z; Bs[c4 + 3][j] = v.w;
        }
        __syncthreads();
        #pragma unroll
        for (int k = 0; k < BK; k++) {
            float4 a0 = *(const float4*)&As[k][ty * TM + 0];
            float4 a1 = *(const float4*)&As[k][ty * TM + 4];
            float4 b0 = *(const float4*)&Bs[k][tx * TN + 0];
            float4 b1v = *(const float4*)&Bs[k][tx * TN + 4];
            float a[TM] = {a0.x, a0.y, a0.z, a0.w, a1.x, a1.y, a1.z, a1.w};
            float b[TN] = {b0.x, b0.y, b0.z, b0.w, b1v.x, b1v.y, b1v.z, b1v.w};
            #pragma unroll
            for (int i = 0; i < TM; i++)
                #pragma unroll
                for (int j = 0; j < TN; j++)
                    acc[i][j] += a[i] * b[j];
        }
        __syncthreads();
    }
    #pragma unroll
    for (int i = 0; i < TM; i++) {
        int grow = block_row + ty * TM + i;
        if (grow >= M) break;
        #pragma unroll
        for (int j = 0; j < TN; j += 4) {
            float4 v = make_float4(acc[i][j], acc[i][j+1], acc[i][j+2], acc[i][j+3]);
            *(float4*)(g_accs + (size_t)grow * D + tx * TN + j) = v;
        }
    }
}

// gemm_agg: acc = g_agg1 @ W1l^T + g_accs; relu; fused W2 projection -> g_zs
__global__ __launch_bounds__(256, 2)
void gemm_agg_kernel(const float* __restrict__ W1l, const float* __restrict__ b1,
                     const float* __restrict__ W2l, const float* __restrict__ W2r,
                     const float* __restrict__ b2, int M) {
    __shared__ float As[BK][BM];
    __shared__ float Bs[BK][BN];
    int block_row = blockIdx.x * BM;
    int tid = threadIdx.x;
    int tx = tid & 15;
    int ty = tid >> 4;
    float acc[TM][TN];
    #pragma unroll
    for (int i = 0; i < TM; i++)
        #pragma unroll
        for (int j = 0; j < TN; j++) acc[i][j] = 0.f;

    #pragma unroll 1
    for (int kt = 0; kt < D; kt += BK) {
        #pragma unroll
        for (int p = 0; p < 2; p++) {
            int f = tid + p * 256;
            int r = f >> 2;
            int c4 = (f & 3) * 4;
            int grow = block_row + r;
            float4 v = make_float4(0.f, 0.f, 0.f, 0.f);
            if (grow < M)
                v = *(const float4*)(g_agg1 + (size_t)grow * D + kt + c4);
            As[c4 + 0][r] = v.x; As[c4 + 1][r] = v.y;
            As[c4 + 2][r] = v.z; As[c4 + 3][r] = v.w;
        }
        #pragma unroll
        for (int p = 0; p < 2; p++) {
            int f = tid + p * 256;
            int j = f >> 2;
            int c4 = (f & 3) * 4;
            float4 v = *(const float4*)(W1l + (size_t)j * D + kt + c4);
            Bs[c4 + 0][j] = v.x; Bs[c4 + 1][j] = v.y;
            Bs[c4 + 2][j] = v.z; Bs[c4 + 3][j] = v.w;
        }
        __syncthreads();
        #pragma unroll
        for (int k = 0; k < BK; k++) {
            float4 a0 = *(const float4*)&As[k][ty * TM + 0];
            float4 a1 = *(const float4*)&As[k][ty * TM + 4];
            float4 b0 = *(const float4*)&Bs[k][tx * TN + 0];
            float4 b1v = *(const float4*)&Bs[k][tx * TN + 4];
            float a[TM] = {a0.x, a0.y, a0.z, a0.w, a1.x, a1.y, a1.z, a1.w};
            float b[TN] = {b0.x, b0.y, b0.z, b0.w, b1v.x, b1v.y, b1v.z, b1v.w};
            #pragma unroll
            for (int i = 0; i < TM; i++)
                #pragma unroll
                for (int j = 0; j < TN; j++)
                    acc[i][j] += a[i] * b[j];
        }
        __syncthreads();
    }

    // ---- epilogue: add self acc, bias + relu, project to z/s ----
    int col0 = tx * TN;
    float wl0[TN], wl1[TN], wr0[TN], wr1[TN];
    #pragma unroll
    for (int j = 0; j < TN; j += 4) {
        float4 a = *(const float4*)(W2l + col0 + j);
        wl0[j] = a.x; wl0[j+1] = a.y; wl0[j+2] = a.z; wl0[j+3] = a.w;
        float4 b = *(const float4*)(W2l + D + col0 + j);
        wl1[j] = b.x; wl1[j+1] = b.y; wl1[j+2] = b.z; wl1[j+3] = b.w;
        float4 c = *(const float4*)(W2r + col0 + j);
        wr0[j] = c.x; wr0[j+1] = c.y; wr0[j+2] = c.z; wr0[j+3] = c.w;
        float4 d = *(const float4*)(W2r + D + col0 + j);
        wr1[j] = d.x; wr1[j+1] = d.y; wr1[j+2] = d.z; wr1[j+3] = d.w;
    }
    float bb2x = b2[0], bb2y = b2[1];

    #pragma unroll
    for (int i = 0; i < TM; i++) {
        int grow = block_row + ty * TM + i;
        float z0 = 0.f, z1 = 0.f, s0 = 0.f, s1 = 0.f;
        if (grow < M) {
            float4 sa = *(const float4*)(g_accs + (size_t)grow * D + col0);
            float4 sb = *(const float4*)(g_accs + (size_t)grow * D + col0 + 4);
            float self[TN] = {sa.x, sa.y, sa.z, sa.w, sb.x, sb.y, sb.z, sb.w};
            #pragma unroll
            for (int j = 0; j < TN; j++) {
                float h = fmaxf(acc[i][j] + self[j] + b1[col0 + j], 0.f);
                z0 += h * wl0[j];
                z1 += h * wl1[j];
                s0 += h * wr0[j];
                s1 += h * wr1[j];
            }
        }
        #pragma unroll
        for (int o = 8; o; o >>= 1) {
            z0 += __shfl_xor_sync(0xffffffffu, z0, o);
            z1 += __shfl_xor_sync(0xffffffffu, z1, o);
            s0 += __shfl_xor_sync(0xffffffffu, s0, o);
            s1 += __shfl_xor_sync(0xffffffffu, s1, o);
        }
        if (tx == 0 && grow < M) {
            float4 o4;
            o4.x = z0; o4.y = z1;
            o4.z = s0 + bb2x; o4.w = s1 + bb2y;
            *(float4*)(g_zs + (size_t)grow * 4) = o4;
        }
    }
}

// ---------------- layer-2 gather + final output ------------------------------
__global__ __launch_bounds__(256)
void final_kernel(float* __restrict__ out, int M) {
    int node = blockIdx.x * blockDim.x + threadIdx.x;
    if (node >= M) return;
    int beg = g_offs[node];
    int end = g_offs[node + 1];
    float a0 = 0.f, a1 = 0.f;
    #pragma unroll 4
    for (int k = beg; k < end; k++) {
        int s = g_csr[k];
        float2 zv = *(const float2*)(g_zs + (size_t)s * 4);
        a0 += zv.x;
        a1 += zv.y;
    }
    float inv = g_inv[node];
    float2 st = *(const float2*)(g_zs + (size_t)node * 4 + 2);
    float2 o;
    o.x = a0 * inv + st.x;
    o.y = a1 * inv + st.y;
    *(float2*)(out + (size_t)node * 2) = o;
}

// ------------------------- launch -------------------------------------------
extern "C" void kernel_launch(void* const* d_in, const int* in_sizes, int n_in,
                              void* d_out, int out_size) {
    const float* x   = (const float*)d_in[0];
    const void*  ei  = d_in[1];
    const float* W1l = (const float*)d_in[2];
    const float* W1r = (const float*)d_in[3];
    const float* b1  = (const float*)d_in[4];
    const float* W2l = (const float*)d_in[5];
    const float* W2r = (const float*)d_in[6];
    const float* b2  = (const float*)d_in[7];
    float* out = (float*)d_out;

    int M = in_sizes[0] / D;
    long long E = in_sizes[1] / 2;
    int nb = (M + SCAN_B - 1) / SCAN_B;
    int nb_gemm = (M + BM - 1) / BM;

    // One-time stream/event creation (host objects only; happens on the
    // uncaptured correctness call first, reused during capture/replay).
    static cudaStream_t s2 = nullptr;
    static cudaEvent_t evFork = nullptr, evJoin = nullptr;
    if (s2 == nullptr) {
        cudaStreamCreateWithFlags(&s2, cudaStreamNonBlocking);
        cudaEventCreateWithFlags(&evFork, cudaEventDisableTiming);
        cudaEventCreateWithFlags(&evJoin, cudaEventDisableTiming);
    }

    // Fork: gemm_self (independent of edges) on side stream.
    cudaEventRecord(evFork, 0);
    cudaStreamWaitEvent(s2, evFork, 0);
    gemm_self_kernel<<<nb_gemm, 256, 0, s2>>>(x, W1r, M);
    cudaEventRecord(evJoin, s2);

    // Main chain: CSR plumbing + aggregation (L2-bound, overlaps gemm_self).
    detect_zero_kernel<<<(M + 255) / 256, 256>>>(ei, M);
    hist_kernel<<<(int)((E + 255) / 256), 256>>>(ei, E);
    scan_p1<<<nb, SCAN_B>>>(M);
    scan_p2<<<1, SCAN_B>>>(nb);
    scan_p3<<<nb, SCAN_B>>>(M);
    build_kernel<<<(int)((E + 255) / 256), 256>>>(ei, E);
    {
        long long threads = (long long)M * 32;
        agg1_gather<<<(int)((threads + 255) / 256), 256>>>(x, M);
    }

    // Join, then the dependent GEMM + output.
    cudaStreamWaitEvent(0, evJoin, 0);
    gemm_agg_kernel<<<nb_gemm, 256>>>(W1l, b1, W2l, W2r, b2, M);
    final_kernel<<<(M + 255) / 256, 256>>>(out, M);
}

// round 9
// speedup vs baseline: 1.3268x; 1.1445x over previous
#include <cuda_runtime.h>
#include <cuda_bf16.h>
#include <mma.h>
#include <cstdint>

using namespace nvcuda;

#define MAX_N 50000
#define MAX_E 800000
#define D 128
#define SCAN_B 256
#define MAX_NB ((MAX_N + SCAN_B - 1) / SCAN_B)   // 196

// ------------------------- scratch (device globals) -------------------------
// g_agg1 padded by 128 rows so the tail wmma CTA can read past M harmlessly.
__device__ float g_agg1[(size_t)(MAX_N + 128) * D];
__device__ float g_xtail[128 * D];            // zero-padded copy of last x rows
__device__ int   g_cnt[MAX_N];
__device__ float g_inv[MAX_N];
__device__ int   g_offs[MAX_N + 1];
__device__ int   g_cursor[MAX_N];
__device__ int   g_csr[MAX_E];
__device__ float g_zs[(size_t)MAX_N * 4];     // z0,z1 (h@W2l^T), s0,s1 (h@W2r^T+b2)
__device__ int   g_blocksum[MAX_NB];
__device__ int   g_blockbase[MAX_NB];
__device__ int   g_is64;

// ------------------------- helpers ------------------------------------------
__device__ __forceinline__ long long load_idx(const void* ei, long long i) {
    if (g_is64) return ((const long long*)ei)[i];
    return (long long)((const int*)ei)[i];
}

// Zero g_cnt; thread 0 detects index dtype (int64 => odd 32-bit words all 0).
__global__ void detect_zero_kernel(const void* ei, int n) {
    int i = blockIdx.x * blockDim.x + threadIdx.x;
    if (i < n) g_cnt[i] = 0;
    if (blockIdx.x == 0 && threadIdx.x == 0) {
        const unsigned* u = (const unsigned*)ei;
        int ok = 1;
        for (int k = 0; k < 64; k++)
            if (u[2 * k + 1] != 0u) { ok = 0; break; }
        g_is64 = ok;
    }
}

// Copy last partial block of x rows into zero-padded g_xtail.
__global__ void xtail_kernel(const float* __restrict__ x, int M, int nfull) {
    int i = blockIdx.x * blockDim.x + threadIdx.x;   // 0 .. 128*128-1
    if (i >= 128 * D) return;
    int row = nfull * 128 + (i >> 7);
    g_xtail[i] = (row < M) ? x[(size_t)row * D + (i & 127)] : 0.f;
}

__global__ void hist_kernel(const void* __restrict__ ei, long long E) {
    long long e = (long long)blockIdx.x * blockDim.x + threadIdx.x;
    if (e >= E) return;
    int d = (int)load_idx(ei, E + e);
    atomicAdd(&g_cnt[d], 1);
}

// ---------------- 3-phase device-wide exclusive scan -------------------------
__global__ __launch_bounds__(SCAN_B)
void scan_p1(int n) {
    __shared__ int wsum[SCAN_B / 32];
    int i = blockIdx.x * SCAN_B + threadIdx.x;
    int lane = threadIdx.x & 31;
    int wid = threadIdx.x >> 5;
    int v = (i < n) ? g_cnt[i] : 0;
    #pragma unroll
    for (int o = 16; o; o >>= 1) v += __shfl_xor_sync(0xffffffffu, v, o);
    if (lane == 0) wsum[wid] = v;
    __syncthreads();
    if (threadIdx.x == 0) {
        int s = 0;
        #pragma unroll
        for (int w = 0; w < SCAN_B / 32; w++) s += wsum[w];
        g_blocksum[blockIdx.x] = s;
    }
}

// All 32 lanes of warp 0 run the 2nd-level scan (full mask; lanes >= 8 carry 0).
__global__ __launch_bounds__(SCAN_B)
void scan_p2(int nb) {
    __shared__ int wsum[SCAN_B / 32];
    int t = threadIdx.x;
    int lane = t & 31;
    int wid = t >> 5;
    int v = (t < nb) ? g_blocksum[t] : 0;
    int inc = v;
    #pragma unroll
    for (int o = 1; o < 32; o <<= 1) {
        int u = __shfl_up_sync(0xffffffffu, inc, o);
        if (lane >= o) inc += u;
    }
    if (lane == 31) wsum[wid] = inc;
    __syncthreads();
    if (wid == 0) {
        int w = (lane < SCAN_B / 32) ? wsum[lane] : 0;
        int winc = w;
        #pragma unroll
        for (int o = 1; o < 32; o <<= 1) {
            int u = __shfl_up_sync(0xffffffffu, winc, o);
            if (lane >= o) winc += u;
        }
        if (lane < SCAN_B / 32) wsum[lane] = winc;
    }
    __syncthreads();
    int base = (wid > 0) ? wsum[wid - 1] : 0;
    if (t < nb) g_blockbase[t] = base + inc - v;
}

__global__ __launch_bounds__(SCAN_B)
void scan_p3(int n) {
    __shared__ int wsum[SCAN_B / 32];
    int i = blockIdx.x * SCAN_B + threadIdx.x;
    int lane = threadIdx.x & 31;
    int wid = threadIdx.x >> 5;
    int c = (i < n) ? g_cnt[i] : 0;
    int inc = c;
    #pragma unroll
    for (int o = 1; o < 32; o <<= 1) {
        int u = __shfl_up_sync(0xffffffffu, inc, o);
        if (lane >= o) inc += u;
    }
    if (lane == 31) wsum[wid] = inc;
    __syncthreads();
    if (wid == 0) {
        int w = (lane < SCAN_B / 32) ? wsum[lane] : 0;
        int winc = w;
        #pragma unroll
        for (int o = 1; o < 32; o <<= 1) {
            int u = __shfl_up_sync(0xffffffffu, winc, o);
            if (lane >= o) winc += u;
        }
        if (lane < SCAN_B / 32) wsum[lane] = winc;
    }
    __syncthreads();
    int wbase = (wid > 0) ? wsum[wid - 1] : 0;
    int off = g_blockbase[blockIdx.x] + wbase + inc - c;
    if (i < n) {
        g_offs[i] = off;
        g_cursor[i] = off;
        g_inv[i] = 1.0f / (float)max(c, 1);
        if (i == n - 1) g_offs[n] = off + c;
    }
}

__global__ void build_kernel(const void* __restrict__ ei, long long E) {
    long long e = (long long)blockIdx.x * blockDim.x + threadIdx.x;
    if (e >= E) return;
    int s = (int)load_idx(ei, e);
    int d = (int)load_idx(ei, E + e);
    int p = atomicAdd(&g_cursor[d], 1);
    g_csr[p] = s;
}

// ---------------- layer-1 gather: warp per node ------------------------------
__global__ __launch_bounds__(256)
void agg1_gather(const float* __restrict__ x, int M) {
    int node = (int)(((long long)blockIdx.x * blockDim.x + threadIdx.x) >> 5);
    int lane = threadIdx.x & 31;
    if (node >= M) return;
    int beg = g_offs[node];
    int end = g_offs[node + 1];
    float4 a0 = make_float4(0.f, 0.f, 0.f, 0.f);
    float4 a1 = make_float4(0.f, 0.f, 0.f, 0.f);
    int k = beg;
    for (; k + 1 < end; k += 2) {
        int s0 = g_csr[k];
        int s1 = g_csr[k + 1];
        float4 v0 = *(const float4*)(x + (size_t)s0 * D + lane * 4);
        float4 v1 = *(const float4*)(x + (size_t)s1 * D + lane * 4);
        a0.x += v0.x; a0.y += v0.y; a0.z += v0.z; a0.w += v0.w;
        a1.x += v1.x; a1.y += v1.y; a1.z += v1.z; a1.w += v1.w;
    }
    if (k < end) {
        int s0 = g_csr[k];
        float4 v0 = *(const float4*)(x + (size_t)s0 * D + lane * 4);
        a0.x += v0.x; a0.y += v0.y; a0.z += v0.z; a0.w += v0.w;
    }
    float inv = g_inv[node];
    float4 r;
    r.x = (a0.x + a1.x) * inv;
    r.y = (a0.y + a1.y) * inv;
    r.z = (a0.z + a1.z) * inv;
    r.w = (a0.w + a1.w) * inv;
    *(float4*)(g_agg1 + (size_t)node * D + lane * 4) = r;
}

// ---------------- wmma tf32 GEMM + fused epilogue ----------------------------
// C[128 x 128] = agg @ W1l^T + x @ W1r^T ; h = relu(C + b1); zs projection.
// 8 warps as 2(m) x 4(n); warp tile 64 x 32 = 4 x 2 frags of 16x16 (k=8).
#define LDC 132
#define WMMA_SMEM (128 * LDC * 4 + 128 * 16 + 128 * 4)   // sC + sW2 + sB1

__global__ __launch_bounds__(256)
void wmma_kernel(const float* __restrict__ x,
                 const float* __restrict__ W1l, const float* __restrict__ W1r,
                 const float* __restrict__ b1,
                 const float* __restrict__ W2l, const float* __restrict__ W2r,
                 const float* __restrict__ b2, int M, int nfull) {
    extern __shared__ float smf[];
    float*  sC  = smf;                          // 128 x 132
    float4* sW2 = (float4*)(smf + 128 * LDC);   // 128 packed W2 cols
    float*  sB1 = smf + 128 * LDC + 512;        // 128

    int tid = threadIdx.x;
    if (tid < 128) {
        sW2[tid] = make_float4(W2l[tid], W2l[D + tid], W2r[tid], W2r[D + tid]);
        sB1[tid] = b1[tid];
    }

    int block_row = blockIdx.x * 128;
    const float* Aself = (blockIdx.x == nfull)
                       ? g_xtail : (x + (size_t)block_row * D);
    const float* Aagg  = g_agg1 + (size_t)block_row * D;   // padded; safe past M

    int wid = tid >> 5;
    int wm = wid >> 2;            // 0..1  (64 rows each)
    int wn = wid & 3;             // 0..3  (32 cols each)

    wmma::fragment<wmma::accumulator, 16, 16, 8, float> c[4][2];
    #pragma unroll
    for (int i = 0; i < 4; i++)
        #pragma unroll
        for (int j = 0; j < 2; j++)
            wmma::fill_fragment(c[i][j], 0.f);

    #pragma unroll 1
    for (int half = 0; half < 2; half++) {
        const float* A = half ? Aself : Aagg;
        const float* B = half ? W1r : W1l;
        #pragma unroll 1
        for (int k = 0; k < D; k += 8) {
            wmma::fragment<wmma::matrix_a, 16, 16, 8, wmma::precision::tf32,
                           wmma::row_major> a[4];
            #pragma unroll
            for (int i = 0; i < 4; i++) {
                wmma::load_matrix_sync(a[i], A + (wm * 64 + i * 16) * D + k, D);
                #pragma unroll
                for (int t = 0; t < a[i].num_elements; t++)
                    a[i].x[t] = wmma::__float_to_tf32(a[i].x[t]);
            }
            wmma::fragment<wmma::matrix_b, 16, 16, 8, wmma::precision::tf32,
                           wmma::col_major> b[2];
            #pragma unroll
            for (int j = 0; j < 2; j++) {
                wmma::load_matrix_sync(b[j], B + (wn * 32 + j * 16) * D + k, D);
                #pragma unroll
                for (int t = 0; t < b[j].num_elements; t++)
                    b[j].x[t] = wmma::__float_to_tf32(b[j].x[t]);
            }
            #pragma unroll
            for (int i = 0; i < 4; i++)
                #pragma unroll
                for (int j = 0; j < 2; j++)
                    wmma::mma_sync(c[i][j], a[i], b[j], c[i][j]);
        }
    }

    #pragma unroll
    for (int i = 0; i < 4; i++)
        #pragma unroll
        for (int j = 0; j < 2; j++)
            wmma::store_matrix_sync(sC + (wm * 64 + i * 16) * LDC + wn * 32 + j * 16,
                                    c[i][j], LDC, wmma::mem_row_major);
    __syncthreads();

    // epilogue: 2 threads per row (64 cols each), fused bias+relu+W2 projection
    int row = tid >> 1;
    int h64 = (tid & 1) * 64;
    float z0 = 0.f, z1 = 0.f, s0 = 0.f, s1 = 0.f;
    const float* crow = sC + row * LDC + h64;
    #pragma unroll 8
    for (int j = 0; j < 64; j++) {
        float h = fmaxf(crow[j] + sB1[h64 + j], 0.f);
        float4 w = sW2[h64 + j];
        z0 += h * w.x; z1 += h * w.y; s0 += h * w.z; s1 += h * w.w;
    }
    z0 += __shfl_xor_sync(0xffffffffu, z0, 1);
    z1 += __shfl_xor_sync(0xffffffffu, z1, 1);
    s0 += __shfl_xor_sync(0xffffffffu, s0, 1);
    s1 += __shfl_xor_sync(0xffffffffu, s1, 1);
    int node = block_row + row;
    if ((tid & 1) == 0 && node < M) {
        float4 o;
        o.x = z0; o.y = z1;
        o.z = s0 + b2[0]; o.w = s1 + b2[1];
        *(float4*)(g_zs + (size_t)node * 4) = o;
    }
}

// ---------------- layer-2 gather + final output ------------------------------
__global__ __launch_bounds__(256)
void final_kernel(float* __restrict__ out, int M) {
    int node = blockIdx.x * blockDim.x + threadIdx.x;
    if (node >= M) return;
    int beg = g_offs[node];
    int end = g_offs[node + 1];
    float a0 = 0.f, a1 = 0.f;
    #pragma unroll 4
    for (int k = beg; k < end; k++) {
        int s = g_csr[k];
        float2 zv = *(const float2*)(g_zs + (size_t)s * 4);
        a0 += zv.x;
        a1 += zv.y;
    }
    float inv = g_inv[node];
    float2 st = *(const float2*)(g_zs + (size_t)node * 4 + 2);
    float2 o;
    o.x = a0 * inv + st.x;
    o.y = a1 * inv + st.y;
    *(float2*)(out + (size_t)node * 2) = o;
}

// ------------------------- launch -------------------------------------------
extern "C" void kernel_launch(void* const* d_in, const int* in_sizes, int n_in,
                              void* d_out, int out_size) {
    const float* x   = (const float*)d_in[0];
    const void*  ei  = d_in[1];
    const float* W1l = (const float*)d_in[2];
    const float* W1r = (const float*)d_in[3];
    const float* b1  = (const float*)d_in[4];
    const float* W2l = (const float*)d_in[5];
    const float* W2r = (const float*)d_in[6];
    const float* b2  = (const float*)d_in[7];
    float* out = (float*)d_out;

    int M = in_sizes[0] / D;
    long long E = in_sizes[1] / 2;
    int nb = (M + SCAN_B - 1) / SCAN_B;
    int nfull = M / 128;

    static bool inited = false;
    if (!inited) {
        cudaFuncSetAttribute(wmma_kernel,
                             cudaFuncAttributeMaxDynamicSharedMemorySize,
                             WMMA_SMEM);
        inited = true;
    }

    xtail_kernel<<<(128 * D + 255) / 256, 256>>>(x, M, nfull);
    detect_zero_kernel<<<(M + 255) / 256, 256>>>(ei, M);
    hist_kernel<<<(int)((E + 255) / 256), 256>>>(ei, E);
    scan_p1<<<nb, SCAN_B>>>(M);
    scan_p2<<<1, SCAN_B>>>(nb);
    scan_p3<<<nb, SCAN_B>>>(M);
    build_kernel<<<(int)((E + 255) / 256), 256>>>(ei, E);
    {
        long long threads = (long long)M * 32;
        agg1_gather<<<(int)((threads + 255) / 256), 256>>>(x, M);
    }
    wmma_kernel<<<nfull + 1, 256, WMMA_SMEM>>>(x, W1l, W1r, b1,
                                               W2l, W2r, b2, M, nfull);
    final_kernel<<<(M + 255) / 256, 256>>>(out, M);
}